// round 14
// baseline (speedup 1.0000x reference)
#include <cuda_runtime.h>
#include <cuda_bf16.h>
#include <stdint.h>
#include <string.h>

#define B_SZ 4
#define S_SZ 4096
#define D_SZ 1024
#define H_SZ 16
#define K_SZ 64
#define W_SZ 8
#define SW_SZ 512
#define M_ROWS (B_SZ * S_SZ)   // 16384

// ---- scratch ----------------------------------------------------------------
__device__ __nv_bfloat16 g_xb[M_ROWS * D_SZ];
__device__ __nv_bfloat16 g_wq[D_SZ * D_SZ];
__device__ __nv_bfloat16 g_wk[D_SZ * D_SZ];
__device__ __nv_bfloat16 g_wv[D_SZ * D_SZ];
__device__ __nv_bfloat16 g_wo[D_SZ * D_SZ];
__device__ __nv_bfloat16 g_q[M_ROWS * D_SZ];
__device__ __nv_bfloat16 g_k[M_ROWS * D_SZ];
__device__ __nv_bfloat16 g_v[M_ROWS * D_SZ];
__device__ __nv_bfloat16 g_ctx[M_ROWS * D_SZ];

// ---- PTX helpers (mma.sync path — tcgen05 rejected by this ptxas) -----------
static __device__ __forceinline__ uint32_t smem_u32(const void* p) {
    return (uint32_t)__cvta_generic_to_shared(p);
}
static __device__ __forceinline__ void ldsm_x4(uint32_t& r0, uint32_t& r1, uint32_t& r2, uint32_t& r3, const void* p) {
    asm volatile("ldmatrix.sync.aligned.m8n8.x4.shared.b16 {%0,%1,%2,%3}, [%4];\n"
                 : "=r"(r0), "=r"(r1), "=r"(r2), "=r"(r3) : "r"(smem_u32(p)));
}
static __device__ __forceinline__ void ldsm_x4t(uint32_t& r0, uint32_t& r1, uint32_t& r2, uint32_t& r3, const void* p) {
    asm volatile("ldmatrix.sync.aligned.m8n8.x4.trans.shared.b16 {%0,%1,%2,%3}, [%4];\n"
                 : "=r"(r0), "=r"(r1), "=r"(r2), "=r"(r3) : "r"(smem_u32(p)));
}
static __device__ __forceinline__ void mma16816(float c[4], const uint32_t a[4], const uint32_t b[2]) {
    asm volatile("mma.sync.aligned.m16n8k16.row.col.f32.bf16.bf16.f32 "
                 "{%0,%1,%2,%3}, {%4,%5,%6,%7}, {%8,%9}, {%0,%1,%2,%3};\n"
                 : "+f"(c[0]), "+f"(c[1]), "+f"(c[2]), "+f"(c[3])
                 : "r"(a[0]), "r"(a[1]), "r"(a[2]), "r"(a[3]), "r"(b[0]), "r"(b[1]));
}
static __device__ __forceinline__ void cp16(const void* sdst, const void* gsrc) {
    asm volatile("cp.async.cg.shared.global [%0], [%1], 16;\n" ::"r"(smem_u32(sdst)), "l"(gsrc));
}
static __device__ __forceinline__ void cp_commit() { asm volatile("cp.async.commit_group;\n"); }
static __device__ __forceinline__ void cp_wait1()  { asm volatile("cp.async.wait_group 1;\n"); }
static __device__ __forceinline__ void cp_wait2()  { asm volatile("cp.async.wait_group 2;\n"); }
static __device__ __forceinline__ uint32_t pack_bf16x2(float lo, float hi) {
    __nv_bfloat162 t = __floats2bfloat162_rn(lo, hi);
    uint32_t u;
    memcpy(&u, &t, 4);
    return u;
}

// ---- fp32 -> bf16 converts --------------------------------------------------
__global__ void cvt4_kernel(const float* __restrict__ in, __nv_bfloat16* __restrict__ out, int n4) {
    int i = blockIdx.x * blockDim.x + threadIdx.x;
    if (i < n4) {
        float4 v = reinterpret_cast<const float4*>(in)[i];
        __nv_bfloat162* o2 = reinterpret_cast<__nv_bfloat162*>(out);
        o2[2 * i]     = __floats2bfloat162_rn(v.x, v.y);
        o2[2 * i + 1] = __floats2bfloat162_rn(v.z, v.w);
    }
}

// all four 1024x1024 weights in one launch; blockIdx.y selects the matrix
__global__ void cvt4w_kernel(const float* __restrict__ w0, const float* __restrict__ w1,
                             const float* __restrict__ w2, const float* __restrict__ w3,
                             __nv_bfloat16* __restrict__ o0, __nv_bfloat16* __restrict__ o1,
                             __nv_bfloat16* __restrict__ o2o, __nv_bfloat16* __restrict__ o3) {
    const int sel = blockIdx.y;
    const float* in = sel == 0 ? w0 : (sel == 1 ? w1 : (sel == 2 ? w2 : w3));
    __nv_bfloat16* out = sel == 0 ? o0 : (sel == 1 ? o1 : (sel == 2 ? o2o : o3));
    int i = blockIdx.x * blockDim.x + threadIdx.x;
    float4 v = reinterpret_cast<const float4*>(in)[i];
    __nv_bfloat162* o2 = reinterpret_cast<__nv_bfloat162*>(out);
    o2[2 * i]     = __floats2bfloat162_rn(v.x, v.y);
    o2[2 * i + 1] = __floats2bfloat162_rn(v.z, v.w);
}

// ---- NN GEMM v2 (R12-proven): BM=128, BN=128, BK=64, 2 CTAs/SM --------------
#define BM 128
#define BN 128
#define BK 64
#define KT (D_SZ / BK)          // 16
#define NSTG 3
#define AS_STRIDE (BK + 8)      // 72
#define BS_STRIDE (BN + 8)      // 136
#define SMEM_GEMM ((NSTG * BM * AS_STRIDE + NSTG * BK * BS_STRIDE) * 2)  // 107520

template <int MODE>
static __device__ __forceinline__ void gemm_body(const __nv_bfloat16* __restrict__ A,
                                                 const __nv_bfloat16* __restrict__ Bm,
                                                 const float* __restrict__ bias,
                                                 const float* __restrict__ resid,
                                                 void* __restrict__ Cout,
                                                 int tm, int tn,
                                                 __nv_bfloat16* As, __nv_bfloat16* Bs) {
    const int tid = threadIdx.x, lane = tid & 31, warp = tid >> 5;
    const int wm = warp >> 2, wn = warp & 3;   // 2x4 warps; warp tile 64x32

    float c[4][4][4];
#pragma unroll
    for (int mi = 0; mi < 4; mi++)
#pragma unroll
        for (int ni = 0; ni < 4; ni++)
#pragma unroll
            for (int j = 0; j < 4; j++) c[mi][ni][j] = 0.f;

    auto load_stage = [&](int s, int k0) {
        __nv_bfloat16* as = As + s * BM * AS_STRIDE;
        __nv_bfloat16* bs = Bs + s * BK * BS_STRIDE;
#pragma unroll
        for (int t = 0; t < 4; t++) {
            int idx = tid + t * 256;
            int r = idx >> 3, ca = (idx & 7) * 8;
            cp16(&as[r * AS_STRIDE + ca], A + (size_t)(tm + r) * D_SZ + k0 + ca);
        }
#pragma unroll
        for (int t = 0; t < 4; t++) {
            int idx = tid + t * 256;
            int r = idx >> 4, cb = (idx & 15) * 8;
            cp16(&bs[r * BS_STRIDE + cb], Bm + (size_t)(k0 + r) * D_SZ + tn + cb);
        }
        cp_commit();
    };

    load_stage(0, 0);
    load_stage(1, BK);

    for (int kt = 0; kt < KT; ++kt) {
        cp_wait1();
        __syncthreads();
        if (kt + 2 < KT) load_stage((kt + 2) % NSTG, (kt + 2) * BK);

        const __nv_bfloat16* as = As + (kt % NSTG) * BM * AS_STRIDE;
        const __nv_bfloat16* bs = Bs + (kt % NSTG) * BK * BS_STRIDE;
#pragma unroll
        for (int kk = 0; kk < BK; kk += 16) {
            uint32_t a[4][4], b[4][2];
#pragma unroll
            for (int mi = 0; mi < 4; mi++)
                ldsm_x4(a[mi][0], a[mi][1], a[mi][2], a[mi][3],
                        &as[(wm * 64 + mi * 16 + (lane & 15)) * AS_STRIDE + kk + (lane >> 4) * 8]);
#pragma unroll
            for (int nj = 0; nj < 2; nj++) {
                uint32_t r0, r1, r2, r3;
                ldsm_x4t(r0, r1, r2, r3,
                         &bs[(kk + (lane & 15)) * BS_STRIDE + wn * 32 + nj * 16 + (lane >> 4) * 8]);
                b[2 * nj][0] = r0; b[2 * nj][1] = r1;
                b[2 * nj + 1][0] = r2; b[2 * nj + 1][1] = r3;
            }
#pragma unroll
            for (int mi = 0; mi < 4; mi++)
#pragma unroll
                for (int ni = 0; ni < 4; ni++)
                    mma16816(c[mi][ni], a[mi], b[ni]);
        }
    }

#pragma unroll
    for (int mi = 0; mi < 4; mi++)
#pragma unroll
        for (int ni = 0; ni < 4; ni++) {
            int col = tn + wn * 32 + ni * 8 + 2 * (lane & 3);
            float b0 = bias[col], b1 = bias[col + 1];
#pragma unroll
            for (int h = 0; h < 2; h++) {
                int row = tm + wm * 64 + mi * 16 + (lane >> 2) + h * 8;
                size_t off = (size_t)row * D_SZ + col;
                float v0 = c[mi][ni][h * 2 + 0] + b0;
                float v1 = c[mi][ni][h * 2 + 1] + b1;
                if (MODE == 0) {
                    *reinterpret_cast<__nv_bfloat162*>(
                        reinterpret_cast<__nv_bfloat16*>(Cout) + off) = __floats2bfloat162_rn(v0, v1);
                } else {
                    float2 r = *reinterpret_cast<const float2*>(resid + off);
                    *reinterpret_cast<float2*>(reinterpret_cast<float*>(Cout) + off) =
                        make_float2(v0 + r.x, v1 + r.y);
                }
            }
        }
}

__launch_bounds__(256, 2)
__global__ void qkv_gemm_kernel(const __nv_bfloat16* __restrict__ A,
                                const __nv_bfloat16* __restrict__ Wq,
                                const __nv_bfloat16* __restrict__ Wk,
                                const __nv_bfloat16* __restrict__ Wv,
                                const float* __restrict__ bq,
                                const float* __restrict__ bk,
                                const float* __restrict__ bv,
                                __nv_bfloat16* __restrict__ qo,
                                __nv_bfloat16* __restrict__ ko,
                                __nv_bfloat16* __restrict__ vo) {
    extern __shared__ __align__(16) __nv_bfloat16 gsm[];
    const int sel = blockIdx.x >> 3;
    const int tn = (blockIdx.x & 7) * BN, tm = blockIdx.y * BM;
    const __nv_bfloat16* Bm = sel == 0 ? Wq : (sel == 1 ? Wk : Wv);
    const float* bias       = sel == 0 ? bq : (sel == 1 ? bk : bv);
    __nv_bfloat16* Cout     = sel == 0 ? qo : (sel == 1 ? ko : vo);
    gemm_body<0>(A, Bm, bias, nullptr, Cout, tm, tn,
                 gsm, gsm + NSTG * BM * AS_STRIDE);
}

__launch_bounds__(256, 2)
__global__ void oproj_gemm_kernel(const __nv_bfloat16* __restrict__ A,
                                  const __nv_bfloat16* __restrict__ Wo,
                                  const float* __restrict__ bo,
                                  const float* __restrict__ resid,
                                  float* __restrict__ out) {
    extern __shared__ __align__(16) __nv_bfloat16 gsm[];
    const int tn = blockIdx.x * BN, tm = blockIdx.y * BM;
    gemm_body<1>(A, Wo, bo, resid, out, tm, tn,
                 gsm, gsm + NSTG * BM * AS_STRIDE);
}

// ---- flash-style windowed attention v5: 2 CTAs/SM, 3-stage K/V pipeline -----
#define AQ 128
#define ACH 64
#define NCH (SW_SZ / ACH)      // 8
#define ASTG 3
#define AST 72
#define SMEM_ATTN ((AQ * AST + ASTG * ACH * AST + ASTG * ACH * AST) * 2)  // 73728

__launch_bounds__(256, 2)
__global__ void attn_kernel(const __nv_bfloat16* __restrict__ Q,
                            const __nv_bfloat16* __restrict__ Kg,
                            const __nv_bfloat16* __restrict__ Vg,
                            __nv_bfloat16* __restrict__ Ctx) {
    extern __shared__ __align__(16) __nv_bfloat16 smbuf[];
    __nv_bfloat16* Qs = smbuf;                                   // [128][72]
    __nv_bfloat16* Ks = smbuf + AQ * AST;                        // [3][64][72]
    __nv_bfloat16* Vs = smbuf + AQ * AST + ASTG * ACH * AST;     // [3][64][72]

    const int tid = threadIdx.x, lane = tid & 31, warp = tid >> 5;
    const int qt = blockIdx.x, head = blockIdx.y, bw = blockIdx.z;
    const int b = bw >> 3, w = bw & 7;
    const size_t rowbase = (size_t)b * S_SZ + (size_t)w * SW_SZ;
    const size_t qrow0 = rowbase + (size_t)qt * AQ;
    const int colbase = head * K_SZ;

    auto load_kv = [&](int st, int ch) {
        for (int i = tid; i < ACH * 8; i += 256) {
            int r = i >> 3, c0 = (i & 7) * 8;
            cp16(&Ks[(st * ACH + r) * AST + c0],
                 &Kg[(rowbase + ch * ACH + r) * D_SZ + colbase + c0]);
            cp16(&Vs[(st * ACH + r) * AST + c0],
                 &Vg[(rowbase + ch * ACH + r) * D_SZ + colbase + c0]);
        }
    };

    for (int i = tid; i < AQ * 8; i += 256) {
        int r = i >> 3, c0 = (i & 7) * 8;
        cp16(&Qs[r * AST + c0], &Q[(qrow0 + r) * D_SZ + colbase + c0]);
    }
    load_kv(0, 0);
    cp_commit();
    load_kv(1, 1);
    cp_commit();
    load_kv(2, 2);
    cp_commit();

    const int qr = warp * 16;
    const float SC_L2E = 0.125f * 1.4426950408889634f;

    uint32_t qa[4][4];
    float l_run[2] = {0.f, 0.f};
    float o[8][4];
#pragma unroll
    for (int f = 0; f < 8; f++)
#pragma unroll
        for (int j = 0; j < 4; j++) o[f][j] = 0.f;

#pragma unroll 1
    for (int ci = 0; ci < NCH; ci++) {
        cp_wait2();                        // chunk ci resident (2 younger may pend)
        __syncthreads();
        if (ci == 0) {
#pragma unroll
            for (int kk = 0; kk < 4; kk++)
                ldsm_x4(qa[kk][0], qa[kk][1], qa[kk][2], qa[kk][3],
                        &Qs[(qr + (lane & 15)) * AST + kk * 16 + (lane >> 4) * 8]);
        }
        const int st = ci % ASTG;

        float s[8][4];
#pragma unroll
        for (int nf = 0; nf < 8; nf++)
#pragma unroll
            for (int j = 0; j < 4; j++) s[nf][j] = 0.f;

#pragma unroll
        for (int kk = 0; kk < 4; kk++) {
#pragma unroll
            for (int nb = 0; nb < 4; nb++) {
                int krow = st * ACH + nb * 16 + ((lane >> 4) << 3) + (lane & 7);
                int kcol = kk * 16 + (((lane >> 3) & 1) << 3);
                uint32_t r0, r1, r2, r3;
                ldsm_x4(r0, r1, r2, r3, &Ks[krow * AST + kcol]);
                uint32_t bb0[2] = {r0, r1}, bb1[2] = {r2, r3};
                mma16816(s[2 * nb], qa[kk], bb0);
                mma16816(s[2 * nb + 1], qa[kk], bb1);
            }
        }

        float psum[2] = {0.f, 0.f};
#pragma unroll
        for (int nf = 0; nf < 8; nf++)
#pragma unroll
            for (int h = 0; h < 2; h++) {
                float e0 = exp2f(s[nf][2 * h]     * SC_L2E);
                float e1 = exp2f(s[nf][2 * h + 1] * SC_L2E);
                s[nf][2 * h] = e0; s[nf][2 * h + 1] = e1;
                psum[h] += e0 + e1;
            }
#pragma unroll
        for (int h = 0; h < 2; h++) {
            psum[h] += __shfl_xor_sync(0xffffffffu, psum[h], 1);
            psum[h] += __shfl_xor_sync(0xffffffffu, psum[h], 2);
            l_run[h] += psum[h];
        }

#pragma unroll
        for (int j = 0; j < 4; j++) {
            uint32_t pa[4];
            pa[0] = pack_bf16x2(s[2 * j][0],     s[2 * j][1]);
            pa[1] = pack_bf16x2(s[2 * j][2],     s[2 * j][3]);
            pa[2] = pack_bf16x2(s[2 * j + 1][0], s[2 * j + 1][1]);
            pa[3] = pack_bf16x2(s[2 * j + 1][2], s[2 * j + 1][3]);
            int vr = st * ACH + j * 16;
#pragma unroll
            for (int vn = 0; vn < 4; vn++) {
                uint32_t r0, r1, r2, r3;
                ldsm_x4t(r0, r1, r2, r3,
                         &Vs[(vr + (lane & 15)) * AST + vn * 16 + (lane >> 4) * 8]);
                uint32_t vb0[2] = {r0, r1}, vb1[2] = {r2, r3};
                mma16816(o[2 * vn], pa, vb0);
                mma16816(o[2 * vn + 1], pa, vb1);
            }
        }

        __syncthreads();                   // all warps done with stage st
        if (ci + ASTG < NCH) load_kv(st, ci + ASTG);
        cp_commit();
    }

#pragma unroll
    for (int h = 0; h < 2; h++) {
        float rinv = 1.0f / l_run[h];
        size_t grow = (qrow0 + qr + (lane >> 2) + 8 * h) * D_SZ;
#pragma unroll
        for (int f = 0; f < 8; f++) {
            int col = colbase + f * 8 + 2 * (lane & 3);
            *reinterpret_cast<__nv_bfloat162*>(&Ctx[grow + col]) =
                __floats2bfloat162_rn(o[f][2 * h] * rinv, o[f][2 * h + 1] * rinv);
        }
    }
}

// ---- LayerNorm (in place), eps = 1e-3 ---------------------------------------
__launch_bounds__(256)
__global__ void ln_kernel(float* __restrict__ y,
                          const float* __restrict__ gamma,
                          const float* __restrict__ beta) {
    const int row = blockIdx.x, t = threadIdx.x;
    float4 v = reinterpret_cast<const float4*>(y + (size_t)row * D_SZ)[t];
    float s = v.x + v.y + v.z + v.w;
    float q = v.x * v.x + v.y * v.y + v.z * v.z + v.w * v.w;
#pragma unroll
    for (int o = 16; o; o >>= 1) {
        s += __shfl_xor_sync(0xffffffffu, s, o);
        q += __shfl_xor_sync(0xffffffffu, q, o);
    }
    __shared__ float ss[8], sq[8];
    int warp = t >> 5, lane = t & 31;
    if (lane == 0) { ss[warp] = s; sq[warp] = q; }
    __syncthreads();
    float ts = 0.f, tq = 0.f;
#pragma unroll
    for (int ww = 0; ww < 8; ww++) { ts += ss[ww]; tq += sq[ww]; }
    float mu = ts * (1.0f / D_SZ);
    float var = tq * (1.0f / D_SZ) - mu * mu;
    float rstd = rsqrtf(var + 1e-3f);
    float4 g  = reinterpret_cast<const float4*>(gamma)[t];
    float4 be = reinterpret_cast<const float4*>(beta)[t];
    float4 o;
    o.x = (v.x - mu) * rstd * g.x + be.x;
    o.y = (v.y - mu) * rstd * g.y + be.y;
    o.z = (v.z - mu) * rstd * g.z + be.z;
    o.w = (v.w - mu) * rstd * g.w + be.w;
    reinterpret_cast<float4*>(y + (size_t)row * D_SZ)[t] = o;
}

// ---- host launcher ----------------------------------------------------------
extern "C" void kernel_launch(void* const* d_in, const int* in_sizes, int n_in,
                              void* d_out, int out_size) {
    const float* x     = (const float*)d_in[0];
    const float* Wq    = (const float*)d_in[1];
    const float* bq    = (const float*)d_in[2];
    const float* Wk    = (const float*)d_in[3];
    const float* bk    = (const float*)d_in[4];
    const float* Wv    = (const float*)d_in[5];
    const float* bv    = (const float*)d_in[6];
    const float* Wo    = (const float*)d_in[7];
    const float* bo    = (const float*)d_in[8];
    const float* gamma = (const float*)d_in[9];
    const float* beta  = (const float*)d_in[10];
    float* out = (float*)d_out;

    void *xb, *wq, *wk, *wv, *wo, *qb, *kb, *vb, *ctxb;
    cudaGetSymbolAddress(&xb, g_xb);
    cudaGetSymbolAddress(&wq, g_wq);
    cudaGetSymbolAddress(&wk, g_wk);
    cudaGetSymbolAddress(&wv, g_wv);
    cudaGetSymbolAddress(&wo, g_wo);
    cudaGetSymbolAddress(&qb, g_q);
    cudaGetSymbolAddress(&kb, g_k);
    cudaGetSymbolAddress(&vb, g_v);
    cudaGetSymbolAddress(&ctxb, g_ctx);

    // side stream for the weight converts (created once; event fork/join is
    // graph-capture legal and deterministic)
    static cudaStream_t s1 = nullptr;
    static cudaEvent_t e_fork = nullptr, e_join = nullptr;
    if (s1 == nullptr) {
        cudaStreamCreateWithFlags(&s1, cudaStreamNonBlocking);
        cudaEventCreateWithFlags(&e_fork, cudaEventDisableTiming);
        cudaEventCreateWithFlags(&e_join, cudaEventDisableTiming);
    }

    // fork: weights convert on s1 concurrently with x convert on main stream
    cudaEventRecord(e_fork, 0);
    cudaStreamWaitEvent(s1, e_fork, 0);
    cvt4w_kernel<<<dim3((D_SZ * D_SZ / 4) / 256, 4), 256, 0, s1>>>(
        Wq, Wk, Wv, Wo,
        (__nv_bfloat16*)wq, (__nv_bfloat16*)wk, (__nv_bfloat16*)wv, (__nv_bfloat16*)wo);
    cudaEventRecord(e_join, s1);

    cvt4_kernel<<<(M_ROWS * D_SZ / 4) / 256, 256>>>(x, (__nv_bfloat16*)xb, M_ROWS * D_SZ / 4);

    // join before QKV (needs wq/wk/wv)
    cudaStreamWaitEvent(0, e_join, 0);

    cudaFuncSetAttribute(qkv_gemm_kernel, cudaFuncAttributeMaxDynamicSharedMemorySize, SMEM_GEMM);
    qkv_gemm_kernel<<<dim3(24, M_ROWS / BM), 256, SMEM_GEMM>>>(
        (const __nv_bfloat16*)xb,
        (const __nv_bfloat16*)wq, (const __nv_bfloat16*)wk, (const __nv_bfloat16*)wv,
        bq, bk, bv,
        (__nv_bfloat16*)qb, (__nv_bfloat16*)kb, (__nv_bfloat16*)vb);

    cudaFuncSetAttribute(attn_kernel, cudaFuncAttributeMaxDynamicSharedMemorySize, SMEM_ATTN);
    attn_kernel<<<dim3(SW_SZ / AQ, H_SZ, B_SZ * W_SZ), 256, SMEM_ATTN>>>(
        (const __nv_bfloat16*)qb, (const __nv_bfloat16*)kb, (const __nv_bfloat16*)vb,
        (__nv_bfloat16*)ctxb);

    cudaFuncSetAttribute(oproj_gemm_kernel, cudaFuncAttributeMaxDynamicSharedMemorySize, SMEM_GEMM);
    oproj_gemm_kernel<<<dim3(D_SZ / BN, M_ROWS / BM), 256, SMEM_GEMM>>>(
        (const __nv_bfloat16*)ctxb, (const __nv_bfloat16*)wo, bo, x, out);

    ln_kernel<<<M_ROWS, 256>>>(out, gamma, beta);
}

// round 15
// speedup vs baseline: 1.0098x; 1.0098x over previous
#include <cuda_runtime.h>
#include <cuda_bf16.h>
#include <stdint.h>
#include <string.h>

#define B_SZ 4
#define S_SZ 4096
#define D_SZ 1024
#define H_SZ 16
#define K_SZ 64
#define W_SZ 8
#define SW_SZ 512
#define M_ROWS (B_SZ * S_SZ)   // 16384

// ---- scratch ----------------------------------------------------------------
__device__ __nv_bfloat16 g_xb[M_ROWS * D_SZ];
__device__ __nv_bfloat16 g_wq[D_SZ * D_SZ];
__device__ __nv_bfloat16 g_wk[D_SZ * D_SZ];
__device__ __nv_bfloat16 g_wv[D_SZ * D_SZ];
__device__ __nv_bfloat16 g_wo[D_SZ * D_SZ];
__device__ __nv_bfloat16 g_q[M_ROWS * D_SZ];
__device__ __nv_bfloat16 g_k[M_ROWS * D_SZ];
__device__ __nv_bfloat16 g_v[M_ROWS * D_SZ];
__device__ __nv_bfloat16 g_ctx[M_ROWS * D_SZ];

// ---- PTX helpers (mma.sync path — tcgen05 rejected by this ptxas) -----------
static __device__ __forceinline__ uint32_t smem_u32(const void* p) {
    return (uint32_t)__cvta_generic_to_shared(p);
}
static __device__ __forceinline__ void ldsm_x4(uint32_t& r0, uint32_t& r1, uint32_t& r2, uint32_t& r3, const void* p) {
    asm volatile("ldmatrix.sync.aligned.m8n8.x4.shared.b16 {%0,%1,%2,%3}, [%4];\n"
                 : "=r"(r0), "=r"(r1), "=r"(r2), "=r"(r3) : "r"(smem_u32(p)));
}
static __device__ __forceinline__ void ldsm_x4t(uint32_t& r0, uint32_t& r1, uint32_t& r2, uint32_t& r3, const void* p) {
    asm volatile("ldmatrix.sync.aligned.m8n8.x4.trans.shared.b16 {%0,%1,%2,%3}, [%4];\n"
                 : "=r"(r0), "=r"(r1), "=r"(r2), "=r"(r3) : "r"(smem_u32(p)));
}
static __device__ __forceinline__ void mma16816(float c[4], const uint32_t a[4], const uint32_t b[2]) {
    asm volatile("mma.sync.aligned.m16n8k16.row.col.f32.bf16.bf16.f32 "
                 "{%0,%1,%2,%3}, {%4,%5,%6,%7}, {%8,%9}, {%0,%1,%2,%3};\n"
                 : "+f"(c[0]), "+f"(c[1]), "+f"(c[2]), "+f"(c[3])
                 : "r"(a[0]), "r"(a[1]), "r"(a[2]), "r"(a[3]), "r"(b[0]), "r"(b[1]));
}
static __device__ __forceinline__ void cp16(const void* sdst, const void* gsrc) {
    asm volatile("cp.async.cg.shared.global [%0], [%1], 16;\n" ::"r"(smem_u32(sdst)), "l"(gsrc));
}
static __device__ __forceinline__ void cp_commit() { asm volatile("cp.async.commit_group;\n"); }
static __device__ __forceinline__ void cp_wait1()  { asm volatile("cp.async.wait_group 1;\n"); }
static __device__ __forceinline__ uint32_t pack_bf16x2(float lo, float hi) {
    __nv_bfloat162 t = __floats2bfloat162_rn(lo, hi);
    uint32_t u;
    memcpy(&u, &t, 4);
    return u;
}

// ---- fp32 -> bf16 converts --------------------------------------------------
__global__ void cvt4_kernel(const float* __restrict__ in, __nv_bfloat16* __restrict__ out, int n4) {
    int i = blockIdx.x * blockDim.x + threadIdx.x;
    if (i < n4) {
        float4 v = reinterpret_cast<const float4*>(in)[i];
        __nv_bfloat162* o2 = reinterpret_cast<__nv_bfloat162*>(out);
        o2[2 * i]     = __floats2bfloat162_rn(v.x, v.y);
        o2[2 * i + 1] = __floats2bfloat162_rn(v.z, v.w);
    }
}

// all four 1024x1024 weights in one launch; blockIdx.y selects the matrix
__global__ void cvt4w_kernel(const float* __restrict__ w0, const float* __restrict__ w1,
                             const float* __restrict__ w2, const float* __restrict__ w3,
                             __nv_bfloat16* __restrict__ o0, __nv_bfloat16* __restrict__ o1,
                             __nv_bfloat16* __restrict__ o2o, __nv_bfloat16* __restrict__ o3) {
    const int sel = blockIdx.y;
    const float* in = sel == 0 ? w0 : (sel == 1 ? w1 : (sel == 2 ? w2 : w3));
    __nv_bfloat16* out = sel == 0 ? o0 : (sel == 1 ? o1 : (sel == 2 ? o2o : o3));
    int i = blockIdx.x * blockDim.x + threadIdx.x;
    float4 v = reinterpret_cast<const float4*>(in)[i];
    __nv_bfloat162* o2 = reinterpret_cast<__nv_bfloat162*>(out);
    o2[2 * i]     = __floats2bfloat162_rn(v.x, v.y);
    o2[2 * i + 1] = __floats2bfloat162_rn(v.z, v.w);
}

// ---- NN GEMM v2 (R12-proven): BM=128, BN=128, BK=64, 2 CTAs/SM --------------
#define BM 128
#define BN 128
#define BK 64
#define KT (D_SZ / BK)          // 16
#define NSTG 3
#define AS_STRIDE (BK + 8)      // 72
#define BS_STRIDE (BN + 8)      // 136
#define SMEM_GEMM ((NSTG * BM * AS_STRIDE + NSTG * BK * BS_STRIDE) * 2)  // 107520

template <int MODE>
static __device__ __forceinline__ void gemm_body(const __nv_bfloat16* __restrict__ A,
                                                 const __nv_bfloat16* __restrict__ Bm,
                                                 const float* __restrict__ bias,
                                                 const float* __restrict__ resid,
                                                 void* __restrict__ Cout,
                                                 int tm, int tn,
                                                 __nv_bfloat16* As, __nv_bfloat16* Bs) {
    const int tid = threadIdx.x, lane = tid & 31, warp = tid >> 5;
    const int wm = warp >> 2, wn = warp & 3;   // 2x4 warps; warp tile 64x32

    float c[4][4][4];
#pragma unroll
    for (int mi = 0; mi < 4; mi++)
#pragma unroll
        for (int ni = 0; ni < 4; ni++)
#pragma unroll
            for (int j = 0; j < 4; j++) c[mi][ni][j] = 0.f;

    auto load_stage = [&](int s, int k0) {
        __nv_bfloat16* as = As + s * BM * AS_STRIDE;
        __nv_bfloat16* bs = Bs + s * BK * BS_STRIDE;
#pragma unroll
        for (int t = 0; t < 4; t++) {
            int idx = tid + t * 256;
            int r = idx >> 3, ca = (idx & 7) * 8;
            cp16(&as[r * AS_STRIDE + ca], A + (size_t)(tm + r) * D_SZ + k0 + ca);
        }
#pragma unroll
        for (int t = 0; t < 4; t++) {
            int idx = tid + t * 256;
            int r = idx >> 4, cb = (idx & 15) * 8;
            cp16(&bs[r * BS_STRIDE + cb], Bm + (size_t)(k0 + r) * D_SZ + tn + cb);
        }
        cp_commit();
    };

    load_stage(0, 0);
    load_stage(1, BK);

    for (int kt = 0; kt < KT; ++kt) {
        cp_wait1();
        __syncthreads();
        if (kt + 2 < KT) load_stage((kt + 2) % NSTG, (kt + 2) * BK);

        const __nv_bfloat16* as = As + (kt % NSTG) * BM * AS_STRIDE;
        const __nv_bfloat16* bs = Bs + (kt % NSTG) * BK * BS_STRIDE;
#pragma unroll
        for (int kk = 0; kk < BK; kk += 16) {
            uint32_t a[4][4], b[4][2];
#pragma unroll
            for (int mi = 0; mi < 4; mi++)
                ldsm_x4(a[mi][0], a[mi][1], a[mi][2], a[mi][3],
                        &as[(wm * 64 + mi * 16 + (lane & 15)) * AS_STRIDE + kk + (lane >> 4) * 8]);
#pragma unroll
            for (int nj = 0; nj < 2; nj++) {
                uint32_t r0, r1, r2, r3;
                ldsm_x4t(r0, r1, r2, r3,
                         &bs[(kk + (lane & 15)) * BS_STRIDE + wn * 32 + nj * 16 + (lane >> 4) * 8]);
                b[2 * nj][0] = r0; b[2 * nj][1] = r1;
                b[2 * nj + 1][0] = r2; b[2 * nj + 1][1] = r3;
            }
#pragma unroll
            for (int mi = 0; mi < 4; mi++)
#pragma unroll
                for (int ni = 0; ni < 4; ni++)
                    mma16816(c[mi][ni], a[mi], b[ni]);
        }
    }

#pragma unroll
    for (int mi = 0; mi < 4; mi++)
#pragma unroll
        for (int ni = 0; ni < 4; ni++) {
            int col = tn + wn * 32 + ni * 8 + 2 * (lane & 3);
            float b0 = bias[col], b1 = bias[col + 1];
#pragma unroll
            for (int h = 0; h < 2; h++) {
                int row = tm + wm * 64 + mi * 16 + (lane >> 2) + h * 8;
                size_t off = (size_t)row * D_SZ + col;
                float v0 = c[mi][ni][h * 2 + 0] + b0;
                float v1 = c[mi][ni][h * 2 + 1] + b1;
                if (MODE == 0) {
                    *reinterpret_cast<__nv_bfloat162*>(
                        reinterpret_cast<__nv_bfloat16*>(Cout) + off) = __floats2bfloat162_rn(v0, v1);
                } else {
                    float2 r = *reinterpret_cast<const float2*>(resid + off);
                    *reinterpret_cast<float2*>(reinterpret_cast<float*>(Cout) + off) =
                        make_float2(v0 + r.x, v1 + r.y);
                }
            }
        }
}

__launch_bounds__(256, 2)
__global__ void qkv_gemm_kernel(const __nv_bfloat16* __restrict__ A,
                                const __nv_bfloat16* __restrict__ Wq,
                                const __nv_bfloat16* __restrict__ Wk,
                                const __nv_bfloat16* __restrict__ Wv,
                                const float* __restrict__ bq,
                                const float* __restrict__ bk,
                                const float* __restrict__ bv,
                                __nv_bfloat16* __restrict__ qo,
                                __nv_bfloat16* __restrict__ ko,
                                __nv_bfloat16* __restrict__ vo) {
    extern __shared__ __align__(16) __nv_bfloat16 gsm[];
    const int sel = blockIdx.x >> 3;
    const int tn = (blockIdx.x & 7) * BN, tm = blockIdx.y * BM;
    const __nv_bfloat16* Bm = sel == 0 ? Wq : (sel == 1 ? Wk : Wv);
    const float* bias       = sel == 0 ? bq : (sel == 1 ? bk : bv);
    __nv_bfloat16* Cout     = sel == 0 ? qo : (sel == 1 ? ko : vo);
    gemm_body<0>(A, Bm, bias, nullptr, Cout, tm, tn,
                 gsm, gsm + NSTG * BM * AS_STRIDE);
}

__launch_bounds__(256, 2)
__global__ void oproj_gemm_kernel(const __nv_bfloat16* __restrict__ A,
                                  const __nv_bfloat16* __restrict__ Wo,
                                  const float* __restrict__ bo,
                                  const float* __restrict__ resid,
                                  float* __restrict__ out) {
    extern __shared__ __align__(16) __nv_bfloat16 gsm[];
    const int tn = blockIdx.x * BN, tm = blockIdx.y * BM;
    gemm_body<1>(A, Wo, bo, resid, out, tm, tn,
                 gsm, gsm + NSTG * BM * AS_STRIDE);
}

// ---- flash-style windowed attention v6 --------------------------------------
// CTA = 128 queries x 512-key window, 128 threads (4 warps x 32 q-rows).
// Each K/V fragment ldsm serves 2 mi-blocks -> crossbar duplication halved.
// 2-stage double-buffered K/V chunks; 2 CTAs/SM.
#define AQ 128
#define ACH 64
#define NCH (SW_SZ / ACH)      // 8
#define AST 72
#define SMEM_ATTN ((AQ * AST + 2 * ACH * AST + 2 * ACH * AST) * 2)  // 55296

__launch_bounds__(128, 2)
__global__ void attn_kernel(const __nv_bfloat16* __restrict__ Q,
                            const __nv_bfloat16* __restrict__ Kg,
                            const __nv_bfloat16* __restrict__ Vg,
                            __nv_bfloat16* __restrict__ Ctx) {
    extern __shared__ __align__(16) __nv_bfloat16 smbuf[];
    __nv_bfloat16* Qs = smbuf;                                // [128][72]
    __nv_bfloat16* Ks = smbuf + AQ * AST;                     // [2][64][72]
    __nv_bfloat16* Vs = smbuf + AQ * AST + 2 * ACH * AST;     // [2][64][72]

    const int tid = threadIdx.x, lane = tid & 31, warp = tid >> 5;
    const int qt = blockIdx.x, head = blockIdx.y, bw = blockIdx.z;
    const int b = bw >> 3, w = bw & 7;
    const size_t rowbase = (size_t)b * S_SZ + (size_t)w * SW_SZ;
    const size_t qrow0 = rowbase + (size_t)qt * AQ;
    const int colbase = head * K_SZ;

    auto load_kv = [&](int st, int ch) {
        for (int i = tid; i < ACH * 8; i += 128) {
            int r = i >> 3, c0 = (i & 7) * 8;
            cp16(&Ks[(st * ACH + r) * AST + c0],
                 &Kg[(rowbase + ch * ACH + r) * D_SZ + colbase + c0]);
            cp16(&Vs[(st * ACH + r) * AST + c0],
                 &Vg[(rowbase + ch * ACH + r) * D_SZ + colbase + c0]);
        }
    };

    for (int i = tid; i < AQ * 8; i += 128) {
        int r = i >> 3, c0 = (i & 7) * 8;
        cp16(&Qs[r * AST + c0], &Q[(qrow0 + r) * D_SZ + colbase + c0]);
    }
    load_kv(0, 0);
    cp_commit();
    load_kv(1, 1);
    cp_commit();

    const int qr = warp * 32;            // warp owns 32 q-rows (2 mi blocks)
    const float SC_L2E = 0.125f * 1.4426950408889634f;

    uint32_t qa[2][4][4];                // [mi][kk][reg]
    float l_run[2][2] = {{0.f, 0.f}, {0.f, 0.f}};
    float o[2][8][4];
#pragma unroll
    for (int mi = 0; mi < 2; mi++)
#pragma unroll
        for (int f = 0; f < 8; f++)
#pragma unroll
            for (int j = 0; j < 4; j++) o[mi][f][j] = 0.f;

#pragma unroll 1
    for (int ci = 0; ci < NCH; ci++) {
        cp_wait1();
        __syncthreads();
        if (ci == 0) {
#pragma unroll
            for (int mi = 0; mi < 2; mi++)
#pragma unroll
                for (int kk = 0; kk < 4; kk++)
                    ldsm_x4(qa[mi][kk][0], qa[mi][kk][1], qa[mi][kk][2], qa[mi][kk][3],
                            &Qs[(qr + mi * 16 + (lane & 15)) * AST + kk * 16 + (lane >> 4) * 8]);
        }
        const int st = ci & 1;

        // ---- S = Qw(32x64) @ Kc(64x64)^T; each K ldsm feeds both mi ---------
        float s[2][8][4];
#pragma unroll
        for (int mi = 0; mi < 2; mi++)
#pragma unroll
            for (int nf = 0; nf < 8; nf++)
#pragma unroll
                for (int j = 0; j < 4; j++) s[mi][nf][j] = 0.f;

#pragma unroll
        for (int kk = 0; kk < 4; kk++) {
#pragma unroll
            for (int nb = 0; nb < 4; nb++) {
                int krow = st * ACH + nb * 16 + ((lane >> 4) << 3) + (lane & 7);
                int kcol = kk * 16 + (((lane >> 3) & 1) << 3);
                uint32_t r0, r1, r2, r3;
                ldsm_x4(r0, r1, r2, r3, &Ks[krow * AST + kcol]);
                uint32_t bb0[2] = {r0, r1}, bb1[2] = {r2, r3};
#pragma unroll
                for (int mi = 0; mi < 2; mi++) {
                    mma16816(s[mi][2 * nb], qa[mi][kk], bb0);
                    mma16816(s[mi][2 * nb + 1], qa[mi][kk], bb1);
                }
            }
        }

        // ---- exp + row-sum (no max shift; scores bounded) -------------------
#pragma unroll
        for (int mi = 0; mi < 2; mi++) {
            float psum[2] = {0.f, 0.f};
#pragma unroll
            for (int nf = 0; nf < 8; nf++)
#pragma unroll
                for (int h = 0; h < 2; h++) {
                    float e0 = exp2f(s[mi][nf][2 * h]     * SC_L2E);
                    float e1 = exp2f(s[mi][nf][2 * h + 1] * SC_L2E);
                    s[mi][nf][2 * h] = e0; s[mi][nf][2 * h + 1] = e1;
                    psum[h] += e0 + e1;
                }
#pragma unroll
            for (int h = 0; h < 2; h++) {
                psum[h] += __shfl_xor_sync(0xffffffffu, psum[h], 1);
                psum[h] += __shfl_xor_sync(0xffffffffu, psum[h], 2);
                l_run[mi][h] += psum[h];
            }
        }

        // ---- PV: P(32x64) @ Vc(64x64); each V ldsm feeds both mi ------------
#pragma unroll
        for (int j = 0; j < 4; j++) {
            uint32_t pa[2][4];
#pragma unroll
            for (int mi = 0; mi < 2; mi++) {
                pa[mi][0] = pack_bf16x2(s[mi][2 * j][0],     s[mi][2 * j][1]);
                pa[mi][1] = pack_bf16x2(s[mi][2 * j][2],     s[mi][2 * j][3]);
                pa[mi][2] = pack_bf16x2(s[mi][2 * j + 1][0], s[mi][2 * j + 1][1]);
                pa[mi][3] = pack_bf16x2(s[mi][2 * j + 1][2], s[mi][2 * j + 1][3]);
            }
            int vr = st * ACH + j * 16;
#pragma unroll
            for (int vn = 0; vn < 4; vn++) {
                uint32_t r0, r1, r2, r3;
                ldsm_x4t(r0, r1, r2, r3,
                         &Vs[(vr + (lane & 15)) * AST + vn * 16 + (lane >> 4) * 8]);
                uint32_t vb0[2] = {r0, r1}, vb1[2] = {r2, r3};
#pragma unroll
                for (int mi = 0; mi < 2; mi++) {
                    mma16816(o[mi][2 * vn], pa[mi], vb0);
                    mma16816(o[mi][2 * vn + 1], pa[mi], vb1);
                }
            }
        }

        __syncthreads();
        if (ci + 2 < NCH) load_kv(st, ci + 2);
        cp_commit();
    }

    // ---- epilogue: normalize, write bf16 ctx --------------------------------
#pragma unroll
    for (int mi = 0; mi < 2; mi++)
#pragma unroll
        for (int h = 0; h < 2; h++) {
            float rinv = 1.0f / l_run[mi][h];
            size_t grow = (qrow0 + qr + mi * 16 + (lane >> 2) + 8 * h) * D_SZ;
#pragma unroll
            for (int f = 0; f < 8; f++) {
                int col = colbase + f * 8 + 2 * (lane & 3);
                *reinterpret_cast<__nv_bfloat162*>(&Ctx[grow + col]) =
                    __floats2bfloat162_rn(o[mi][f][2 * h] * rinv, o[mi][f][2 * h + 1] * rinv);
            }
        }
}

// ---- LayerNorm (in place), eps = 1e-3 ---------------------------------------
__launch_bounds__(256)
__global__ void ln_kernel(float* __restrict__ y,
                          const float* __restrict__ gamma,
                          const float* __restrict__ beta) {
    const int row = blockIdx.x, t = threadIdx.x;
    float4 v = reinterpret_cast<const float4*>(y + (size_t)row * D_SZ)[t];
    float s = v.x + v.y + v.z + v.w;
    float q = v.x * v.x + v.y * v.y + v.z * v.z + v.w * v.w;
#pragma unroll
    for (int o = 16; o; o >>= 1) {
        s += __shfl_xor_sync(0xffffffffu, s, o);
        q += __shfl_xor_sync(0xffffffffu, q, o);
    }
    __shared__ float ss[8], sq[8];
    int warp = t >> 5, lane = t & 31;
    if (lane == 0) { ss[warp] = s; sq[warp] = q; }
    __syncthreads();
    float ts = 0.f, tq = 0.f;
#pragma unroll
    for (int ww = 0; ww < 8; ww++) { ts += ss[ww]; tq += sq[ww]; }
    float mu = ts * (1.0f / D_SZ);
    float var = tq * (1.0f / D_SZ) - mu * mu;
    float rstd = rsqrtf(var + 1e-3f);
    float4 g  = reinterpret_cast<const float4*>(gamma)[t];
    float4 be = reinterpret_cast<const float4*>(beta)[t];
    float4 o;
    o.x = (v.x - mu) * rstd * g.x + be.x;
    o.y = (v.y - mu) * rstd * g.y + be.y;
    o.z = (v.z - mu) * rstd * g.z + be.z;
    o.w = (v.w - mu) * rstd * g.w + be.w;
    reinterpret_cast<float4*>(y + (size_t)row * D_SZ)[t] = o;
}

// ---- host launcher ----------------------------------------------------------
extern "C" void kernel_launch(void* const* d_in, const int* in_sizes, int n_in,
                              void* d_out, int out_size) {
    const float* x     = (const float*)d_in[0];
    const float* Wq    = (const float*)d_in[1];
    const float* bq    = (const float*)d_in[2];
    const float* Wk    = (const float*)d_in[3];
    const float* bk    = (const float*)d_in[4];
    const float* Wv    = (const float*)d_in[5];
    const float* bv    = (const float*)d_in[6];
    const float* Wo    = (const float*)d_in[7];
    const float* bo    = (const float*)d_in[8];
    const float* gamma = (const float*)d_in[9];
    const float* beta  = (const float*)d_in[10];
    float* out = (float*)d_out;

    void *xb, *wq, *wk, *wv, *wo, *qb, *kb, *vb, *ctxb;
    cudaGetSymbolAddress(&xb, g_xb);
    cudaGetSymbolAddress(&wq, g_wq);
    cudaGetSymbolAddress(&wk, g_wk);
    cudaGetSymbolAddress(&wv, g_wv);
    cudaGetSymbolAddress(&wo, g_wo);
    cudaGetSymbolAddress(&qb, g_q);
    cudaGetSymbolAddress(&kb, g_k);
    cudaGetSymbolAddress(&vb, g_v);
    cudaGetSymbolAddress(&ctxb, g_ctx);

    cvt4_kernel<<<(M_ROWS * D_SZ / 4) / 256, 256>>>(x, (__nv_bfloat16*)xb, M_ROWS * D_SZ / 4);
    cvt4w_kernel<<<dim3((D_SZ * D_SZ / 4) / 256, 4), 256>>>(
        Wq, Wk, Wv, Wo,
        (__nv_bfloat16*)wq, (__nv_bfloat16*)wk, (__nv_bfloat16*)wv, (__nv_bfloat16*)wo);

    cudaFuncSetAttribute(qkv_gemm_kernel, cudaFuncAttributeMaxDynamicSharedMemorySize, SMEM_GEMM);
    qkv_gemm_kernel<<<dim3(24, M_ROWS / BM), 256, SMEM_GEMM>>>(
        (const __nv_bfloat16*)xb,
        (const __nv_bfloat16*)wq, (const __nv_bfloat16*)wk, (const __nv_bfloat16*)wv,
        bq, bk, bv,
        (__nv_bfloat16*)qb, (__nv_bfloat16*)kb, (__nv_bfloat16*)vb);

    cudaFuncSetAttribute(attn_kernel, cudaFuncAttributeMaxDynamicSharedMemorySize, SMEM_ATTN);
    attn_kernel<<<dim3(SW_SZ / AQ, H_SZ, B_SZ * W_SZ), 128, SMEM_ATTN>>>(
        (const __nv_bfloat16*)qb, (const __nv_bfloat16*)kb, (const __nv_bfloat16*)vb,
        (__nv_bfloat16*)ctxb);

    cudaFuncSetAttribute(oproj_gemm_kernel, cudaFuncAttributeMaxDynamicSharedMemorySize, SMEM_GEMM);
    oproj_gemm_kernel<<<dim3(D_SZ / BN, M_ROWS / BM), 256, SMEM_GEMM>>>(
        (const __nv_bfloat16*)ctxb, (const __nv_bfloat16*)wo, bo, x, out);

    ln_kernel<<<M_ROWS, 256>>>(out, gamma, beta);
}

// round 16
// speedup vs baseline: 1.0204x; 1.0105x over previous
#include <cuda_runtime.h>
#include <cuda_bf16.h>
#include <stdint.h>
#include <string.h>

#define B_SZ 4
#define S_SZ 4096
#define D_SZ 1024
#define H_SZ 16
#define K_SZ 64
#define W_SZ 8
#define SW_SZ 512
#define M_ROWS (B_SZ * S_SZ)   // 16384

// ---- scratch ----------------------------------------------------------------
__device__ __nv_bfloat16 g_xb[M_ROWS * D_SZ];
__device__ __nv_bfloat16 g_wq[D_SZ * D_SZ];
__device__ __nv_bfloat16 g_wk[D_SZ * D_SZ];
__device__ __nv_bfloat16 g_wv[D_SZ * D_SZ];
__device__ __nv_bfloat16 g_wo[D_SZ * D_SZ];
__device__ __nv_bfloat16 g_q[M_ROWS * D_SZ];
__device__ __nv_bfloat16 g_k[M_ROWS * D_SZ];
__device__ __nv_bfloat16 g_v[M_ROWS * D_SZ];
__device__ __nv_bfloat16 g_ctx[M_ROWS * D_SZ];

// ---- PTX helpers (mma.sync path — tcgen05 rejected by this ptxas) -----------
static __device__ __forceinline__ uint32_t smem_u32(const void* p) {
    return (uint32_t)__cvta_generic_to_shared(p);
}
static __device__ __forceinline__ void ldsm_x4(uint32_t& r0, uint32_t& r1, uint32_t& r2, uint32_t& r3, const void* p) {
    asm volatile("ldmatrix.sync.aligned.m8n8.x4.shared.b16 {%0,%1,%2,%3}, [%4];\n"
                 : "=r"(r0), "=r"(r1), "=r"(r2), "=r"(r3) : "r"(smem_u32(p)));
}
static __device__ __forceinline__ void ldsm_x4t(uint32_t& r0, uint32_t& r1, uint32_t& r2, uint32_t& r3, const void* p) {
    asm volatile("ldmatrix.sync.aligned.m8n8.x4.trans.shared.b16 {%0,%1,%2,%3}, [%4];\n"
                 : "=r"(r0), "=r"(r1), "=r"(r2), "=r"(r3) : "r"(smem_u32(p)));
}
static __device__ __forceinline__ void mma16816(float c[4], const uint32_t a[4], const uint32_t b[2]) {
    asm volatile("mma.sync.aligned.m16n8k16.row.col.f32.bf16.bf16.f32 "
                 "{%0,%1,%2,%3}, {%4,%5,%6,%7}, {%8,%9}, {%0,%1,%2,%3};\n"
                 : "+f"(c[0]), "+f"(c[1]), "+f"(c[2]), "+f"(c[3])
                 : "r"(a[0]), "r"(a[1]), "r"(a[2]), "r"(a[3]), "r"(b[0]), "r"(b[1]));
}
static __device__ __forceinline__ void cp16(const void* sdst, const void* gsrc) {
    asm volatile("cp.async.cg.shared.global [%0], [%1], 16;\n" ::"r"(smem_u32(sdst)), "l"(gsrc));
}
static __device__ __forceinline__ void cp_commit() { asm volatile("cp.async.commit_group;\n"); }
static __device__ __forceinline__ void cp_wait1()  { asm volatile("cp.async.wait_group 1;\n"); }
static __device__ __forceinline__ uint32_t pack_bf16x2(float lo, float hi) {
    __nv_bfloat162 t = __floats2bfloat162_rn(lo, hi);
    uint32_t u;
    memcpy(&u, &t, 4);
    return u;
}

// ---- fp32 -> bf16 converts --------------------------------------------------
// streaming convert with ILP-4 (4 independent float4 loads in flight)
__global__ void cvtx_kernel(const float* __restrict__ in, __nv_bfloat16* __restrict__ out, int n4) {
    const float4* in4 = reinterpret_cast<const float4*>(in);
    __nv_bfloat162* o2 = reinterpret_cast<__nv_bfloat162*>(out);
    const int stride = gridDim.x * blockDim.x;
    for (int i = blockIdx.x * blockDim.x + threadIdx.x; i < n4; i += 4 * stride) {
        float4 v[4];
#pragma unroll
        for (int j = 0; j < 4; j++) {
            int idx = i + j * stride;
            if (idx < n4) v[j] = in4[idx];
        }
#pragma unroll
        for (int j = 0; j < 4; j++) {
            int idx = i + j * stride;
            if (idx < n4) {
                o2[2 * idx]     = __floats2bfloat162_rn(v[j].x, v[j].y);
                o2[2 * idx + 1] = __floats2bfloat162_rn(v[j].z, v[j].w);
            }
        }
    }
}

// all four 1024x1024 weights in one launch; blockIdx.y selects the matrix
__global__ void cvt4w_kernel(const float* __restrict__ w0, const float* __restrict__ w1,
                             const float* __restrict__ w2, const float* __restrict__ w3,
                             __nv_bfloat16* __restrict__ o0, __nv_bfloat16* __restrict__ o1,
                             __nv_bfloat16* __restrict__ o2o, __nv_bfloat16* __restrict__ o3) {
    const int sel = blockIdx.y;
    const float* in = sel == 0 ? w0 : (sel == 1 ? w1 : (sel == 2 ? w2 : w3));
    __nv_bfloat16* out = sel == 0 ? o0 : (sel == 1 ? o1 : (sel == 2 ? o2o : o3));
    int i = blockIdx.x * blockDim.x + threadIdx.x;
    float4 v = reinterpret_cast<const float4*>(in)[i];
    __nv_bfloat162* o2 = reinterpret_cast<__nv_bfloat162*>(out);
    o2[2 * i]     = __floats2bfloat162_rn(v.x, v.y);
    o2[2 * i + 1] = __floats2bfloat162_rn(v.z, v.w);
}

// ---- NN GEMM v2 (R12-proven): BM=128, BN=128, BK=64, 2 CTAs/SM --------------
#define BM 128
#define BN 128
#define BK 64
#define KT (D_SZ / BK)          // 16
#define NSTG 3
#define AS_STRIDE (BK + 8)      // 72
#define BS_STRIDE (BN + 8)      // 136
#define SMEM_GEMM ((NSTG * BM * AS_STRIDE + NSTG * BK * BS_STRIDE) * 2)  // 107520

template <int MODE>
static __device__ __forceinline__ void gemm_body(const __nv_bfloat16* __restrict__ A,
                                                 const __nv_bfloat16* __restrict__ Bm,
                                                 const float* __restrict__ bias,
                                                 const float* __restrict__ resid,
                                                 void* __restrict__ Cout,
                                                 int tm, int tn,
                                                 __nv_bfloat16* As, __nv_bfloat16* Bs) {
    const int tid = threadIdx.x, lane = tid & 31, warp = tid >> 5;
    const int wm = warp >> 2, wn = warp & 3;   // 2x4 warps; warp tile 64x32

    float c[4][4][4];
#pragma unroll
    for (int mi = 0; mi < 4; mi++)
#pragma unroll
        for (int ni = 0; ni < 4; ni++)
#pragma unroll
            for (int j = 0; j < 4; j++) c[mi][ni][j] = 0.f;

    auto load_stage = [&](int s, int k0) {
        __nv_bfloat16* as = As + s * BM * AS_STRIDE;
        __nv_bfloat16* bs = Bs + s * BK * BS_STRIDE;
#pragma unroll
        for (int t = 0; t < 4; t++) {
            int idx = tid + t * 256;
            int r = idx >> 3, ca = (idx & 7) * 8;
            cp16(&as[r * AS_STRIDE + ca], A + (size_t)(tm + r) * D_SZ + k0 + ca);
        }
#pragma unroll
        for (int t = 0; t < 4; t++) {
            int idx = tid + t * 256;
            int r = idx >> 4, cb = (idx & 15) * 8;
            cp16(&bs[r * BS_STRIDE + cb], Bm + (size_t)(k0 + r) * D_SZ + tn + cb);
        }
        cp_commit();
    };

    load_stage(0, 0);
    load_stage(1, BK);

    for (int kt = 0; kt < KT; ++kt) {
        cp_wait1();
        __syncthreads();
        if (kt + 2 < KT) load_stage((kt + 2) % NSTG, (kt + 2) * BK);

        const __nv_bfloat16* as = As + (kt % NSTG) * BM * AS_STRIDE;
        const __nv_bfloat16* bs = Bs + (kt % NSTG) * BK * BS_STRIDE;
#pragma unroll
        for (int kk = 0; kk < BK; kk += 16) {
            uint32_t a[4][4], b[4][2];
#pragma unroll
            for (int mi = 0; mi < 4; mi++)
                ldsm_x4(a[mi][0], a[mi][1], a[mi][2], a[mi][3],
                        &as[(wm * 64 + mi * 16 + (lane & 15)) * AS_STRIDE + kk + (lane >> 4) * 8]);
#pragma unroll
            for (int nj = 0; nj < 2; nj++) {
                uint32_t r0, r1, r2, r3;
                ldsm_x4t(r0, r1, r2, r3,
                         &bs[(kk + (lane & 15)) * BS_STRIDE + wn * 32 + nj * 16 + (lane >> 4) * 8]);
                b[2 * nj][0] = r0; b[2 * nj][1] = r1;
                b[2 * nj + 1][0] = r2; b[2 * nj + 1][1] = r3;
            }
#pragma unroll
            for (int mi = 0; mi < 4; mi++)
#pragma unroll
                for (int ni = 0; ni < 4; ni++)
                    mma16816(c[mi][ni], a[mi], b[ni]);
        }
    }

#pragma unroll
    for (int mi = 0; mi < 4; mi++)
#pragma unroll
        for (int ni = 0; ni < 4; ni++) {
            int col = tn + wn * 32 + ni * 8 + 2 * (lane & 3);
            float b0 = bias[col], b1 = bias[col + 1];
#pragma unroll
            for (int h = 0; h < 2; h++) {
                int row = tm + wm * 64 + mi * 16 + (lane >> 2) + h * 8;
                size_t off = (size_t)row * D_SZ + col;
                float v0 = c[mi][ni][h * 2 + 0] + b0;
                float v1 = c[mi][ni][h * 2 + 1] + b1;
                if (MODE == 0) {
                    *reinterpret_cast<__nv_bfloat162*>(
                        reinterpret_cast<__nv_bfloat16*>(Cout) + off) = __floats2bfloat162_rn(v0, v1);
                } else {
                    float2 r = *reinterpret_cast<const float2*>(resid + off);
                    *reinterpret_cast<float2*>(reinterpret_cast<float*>(Cout) + off) =
                        make_float2(v0 + r.x, v1 + r.y);
                }
            }
        }
}

__launch_bounds__(256, 2)
__global__ void qkv_gemm_kernel(const __nv_bfloat16* __restrict__ A,
                                const __nv_bfloat16* __restrict__ Wq,
                                const __nv_bfloat16* __restrict__ Wk,
                                const __nv_bfloat16* __restrict__ Wv,
                                const float* __restrict__ bq,
                                const float* __restrict__ bk,
                                const float* __restrict__ bv,
                                __nv_bfloat16* __restrict__ qo,
                                __nv_bfloat16* __restrict__ ko,
                                __nv_bfloat16* __restrict__ vo) {
    extern __shared__ __align__(16) __nv_bfloat16 gsm[];
    const int sel = blockIdx.x >> 3;
    const int tn = (blockIdx.x & 7) * BN, tm = blockIdx.y * BM;
    const __nv_bfloat16* Bm = sel == 0 ? Wq : (sel == 1 ? Wk : Wv);
    const float* bias       = sel == 0 ? bq : (sel == 1 ? bk : bv);
    __nv_bfloat16* Cout     = sel == 0 ? qo : (sel == 1 ? ko : vo);
    gemm_body<0>(A, Bm, bias, nullptr, Cout, tm, tn,
                 gsm, gsm + NSTG * BM * AS_STRIDE);
}

__launch_bounds__(256, 2)
__global__ void oproj_gemm_kernel(const __nv_bfloat16* __restrict__ A,
                                  const __nv_bfloat16* __restrict__ Wo,
                                  const float* __restrict__ bo,
                                  const float* __restrict__ resid,
                                  float* __restrict__ out) {
    extern __shared__ __align__(16) __nv_bfloat16 gsm[];
    const int tn = blockIdx.x * BN, tm = blockIdx.y * BM;
    gemm_body<1>(A, Wo, bo, resid, out, tm, tn,
                 gsm, gsm + NSTG * BM * AS_STRIDE);
}

// ---- flash-style windowed attention v6 (R15-proven) -------------------------
#define AQ 128
#define ACH 64
#define NCH (SW_SZ / ACH)      // 8
#define AST 72
#define SMEM_ATTN ((AQ * AST + 2 * ACH * AST + 2 * ACH * AST) * 2)  // 55296

__launch_bounds__(128, 2)
__global__ void attn_kernel(const __nv_bfloat16* __restrict__ Q,
                            const __nv_bfloat16* __restrict__ Kg,
                            const __nv_bfloat16* __restrict__ Vg,
                            __nv_bfloat16* __restrict__ Ctx) {
    extern __shared__ __align__(16) __nv_bfloat16 smbuf[];
    __nv_bfloat16* Qs = smbuf;                                // [128][72]
    __nv_bfloat16* Ks = smbuf + AQ * AST;                     // [2][64][72]
    __nv_bfloat16* Vs = smbuf + AQ * AST + 2 * ACH * AST;     // [2][64][72]

    const int tid = threadIdx.x, lane = tid & 31, warp = tid >> 5;
    const int qt = blockIdx.x, head = blockIdx.y, bw = blockIdx.z;
    const int b = bw >> 3, w = bw & 7;
    const size_t rowbase = (size_t)b * S_SZ + (size_t)w * SW_SZ;
    const size_t qrow0 = rowbase + (size_t)qt * AQ;
    const int colbase = head * K_SZ;

    auto load_kv = [&](int st, int ch) {
        for (int i = tid; i < ACH * 8; i += 128) {
            int r = i >> 3, c0 = (i & 7) * 8;
            cp16(&Ks[(st * ACH + r) * AST + c0],
                 &Kg[(rowbase + ch * ACH + r) * D_SZ + colbase + c0]);
            cp16(&Vs[(st * ACH + r) * AST + c0],
                 &Vg[(rowbase + ch * ACH + r) * D_SZ + colbase + c0]);
        }
    };

    for (int i = tid; i < AQ * 8; i += 128) {
        int r = i >> 3, c0 = (i & 7) * 8;
        cp16(&Qs[r * AST + c0], &Q[(qrow0 + r) * D_SZ + colbase + c0]);
    }
    load_kv(0, 0);
    cp_commit();
    load_kv(1, 1);
    cp_commit();

    const int qr = warp * 32;            // warp owns 32 q-rows (2 mi blocks)
    const float SC_L2E = 0.125f * 1.4426950408889634f;

    uint32_t qa[2][4][4];                // [mi][kk][reg]
    float l_run[2][2] = {{0.f, 0.f}, {0.f, 0.f}};
    float o[2][8][4];
#pragma unroll
    for (int mi = 0; mi < 2; mi++)
#pragma unroll
        for (int f = 0; f < 8; f++)
#pragma unroll
            for (int j = 0; j < 4; j++) o[mi][f][j] = 0.f;

#pragma unroll 1
    for (int ci = 0; ci < NCH; ci++) {
        cp_wait1();
        __syncthreads();
        if (ci == 0) {
#pragma unroll
            for (int mi = 0; mi < 2; mi++)
#pragma unroll
                for (int kk = 0; kk < 4; kk++)
                    ldsm_x4(qa[mi][kk][0], qa[mi][kk][1], qa[mi][kk][2], qa[mi][kk][3],
                            &Qs[(qr + mi * 16 + (lane & 15)) * AST + kk * 16 + (lane >> 4) * 8]);
        }
        const int st = ci & 1;

        float s[2][8][4];
#pragma unroll
        for (int mi = 0; mi < 2; mi++)
#pragma unroll
            for (int nf = 0; nf < 8; nf++)
#pragma unroll
                for (int j = 0; j < 4; j++) s[mi][nf][j] = 0.f;

#pragma unroll
        for (int kk = 0; kk < 4; kk++) {
#pragma unroll
            for (int nb = 0; nb < 4; nb++) {
                int krow = st * ACH + nb * 16 + ((lane >> 4) << 3) + (lane & 7);
                int kcol = kk * 16 + (((lane >> 3) & 1) << 3);
                uint32_t r0, r1, r2, r3;
                ldsm_x4(r0, r1, r2, r3, &Ks[krow * AST + kcol]);
                uint32_t bb0[2] = {r0, r1}, bb1[2] = {r2, r3};
#pragma unroll
                for (int mi = 0; mi < 2; mi++) {
                    mma16816(s[mi][2 * nb], qa[mi][kk], bb0);
                    mma16816(s[mi][2 * nb + 1], qa[mi][kk], bb1);
                }
            }
        }

#pragma unroll
        for (int mi = 0; mi < 2; mi++) {
            float psum[2] = {0.f, 0.f};
#pragma unroll
            for (int nf = 0; nf < 8; nf++)
#pragma unroll
                for (int h = 0; h < 2; h++) {
                    float e0 = exp2f(s[mi][nf][2 * h]     * SC_L2E);
                    float e1 = exp2f(s[mi][nf][2 * h + 1] * SC_L2E);
                    s[mi][nf][2 * h] = e0; s[mi][nf][2 * h + 1] = e1;
                    psum[h] += e0 + e1;
                }
#pragma unroll
            for (int h = 0; h < 2; h++) {
                psum[h] += __shfl_xor_sync(0xffffffffu, psum[h], 1);
                psum[h] += __shfl_xor_sync(0xffffffffu, psum[h], 2);
                l_run[mi][h] += psum[h];
            }
        }

#pragma unroll
        for (int j = 0; j < 4; j++) {
            uint32_t pa[2][4];
#pragma unroll
            for (int mi = 0; mi < 2; mi++) {
                pa[mi][0] = pack_bf16x2(s[mi][2 * j][0],     s[mi][2 * j][1]);
                pa[mi][1] = pack_bf16x2(s[mi][2 * j][2],     s[mi][2 * j][3]);
                pa[mi][2] = pack_bf16x2(s[mi][2 * j + 1][0], s[mi][2 * j + 1][1]);
                pa[mi][3] = pack_bf16x2(s[mi][2 * j + 1][2], s[mi][2 * j + 1][3]);
            }
            int vr = st * ACH + j * 16;
#pragma unroll
            for (int vn = 0; vn < 4; vn++) {
                uint32_t r0, r1, r2, r3;
                ldsm_x4t(r0, r1, r2, r3,
                         &Vs[(vr + (lane & 15)) * AST + vn * 16 + (lane >> 4) * 8]);
                uint32_t vb0[2] = {r0, r1}, vb1[2] = {r2, r3};
#pragma unroll
                for (int mi = 0; mi < 2; mi++) {
                    mma16816(o[mi][2 * vn], pa[mi], vb0);
                    mma16816(o[mi][2 * vn + 1], pa[mi], vb1);
                }
            }
        }

        __syncthreads();
        if (ci + 2 < NCH) load_kv(st, ci + 2);
        cp_commit();
    }

#pragma unroll
    for (int mi = 0; mi < 2; mi++)
#pragma unroll
        for (int h = 0; h < 2; h++) {
            float rinv = 1.0f / l_run[mi][h];
            size_t grow = (qrow0 + qr + mi * 16 + (lane >> 2) + 8 * h) * D_SZ;
#pragma unroll
            for (int f = 0; f < 8; f++) {
                int col = colbase + f * 8 + 2 * (lane & 3);
                *reinterpret_cast<__nv_bfloat162*>(&Ctx[grow + col]) =
                    __floats2bfloat162_rn(o[mi][f][2 * h] * rinv, o[mi][f][2 * h + 1] * rinv);
            }
        }
}

// ---- LayerNorm (in place), eps = 1e-3 ---------------------------------------
__launch_bounds__(256)
__global__ void ln_kernel(float* __restrict__ y,
                          const float* __restrict__ gamma,
                          const float* __restrict__ beta) {
    const int row = blockIdx.x, t = threadIdx.x;
    float4 v = reinterpret_cast<const float4*>(y + (size_t)row * D_SZ)[t];
    float s = v.x + v.y + v.z + v.w;
    float q = v.x * v.x + v.y * v.y + v.z * v.z + v.w * v.w;
#pragma unroll
    for (int o = 16; o; o >>= 1) {
        s += __shfl_xor_sync(0xffffffffu, s, o);
        q += __shfl_xor_sync(0xffffffffu, q, o);
    }
    __shared__ float ss[8], sq[8];
    int warp = t >> 5, lane = t & 31;
    if (lane == 0) { ss[warp] = s; sq[warp] = q; }
    __syncthreads();
    float ts = 0.f, tq = 0.f;
#pragma unroll
    for (int ww = 0; ww < 8; ww++) { ts += ss[ww]; tq += sq[ww]; }
    float mu = ts * (1.0f / D_SZ);
    float var = tq * (1.0f / D_SZ) - mu * mu;
    float rstd = rsqrtf(var + 1e-3f);
    float4 g  = reinterpret_cast<const float4*>(gamma)[t];
    float4 be = reinterpret_cast<const float4*>(beta)[t];
    float4 o;
    o.x = (v.x - mu) * rstd * g.x + be.x;
    o.y = (v.y - mu) * rstd * g.y + be.y;
    o.z = (v.z - mu) * rstd * g.z + be.z;
    o.w = (v.w - mu) * rstd * g.w + be.w;
    reinterpret_cast<float4*>(y + (size_t)row * D_SZ)[t] = o;
}

// ---- host launcher ----------------------------------------------------------
extern "C" void kernel_launch(void* const* d_in, const int* in_sizes, int n_in,
                              void* d_out, int out_size) {
    const float* x     = (const float*)d_in[0];
    const float* Wq    = (const float*)d_in[1];
    const float* bq    = (const float*)d_in[2];
    const float* Wk    = (const float*)d_in[3];
    const float* bk    = (const float*)d_in[4];
    const float* Wv    = (const float*)d_in[5];
    const float* bv    = (const float*)d_in[6];
    const float* Wo    = (const float*)d_in[7];
    const float* bo    = (const float*)d_in[8];
    const float* gamma = (const float*)d_in[9];
    const float* beta  = (const float*)d_in[10];
    float* out = (float*)d_out;

    void *xb, *wq, *wk, *wv, *wo, *qb, *kb, *vb, *ctxb;
    cudaGetSymbolAddress(&xb, g_xb);
    cudaGetSymbolAddress(&wq, g_wq);
    cudaGetSymbolAddress(&wk, g_wk);
    cudaGetSymbolAddress(&wv, g_wv);
    cudaGetSymbolAddress(&wo, g_wo);
    cudaGetSymbolAddress(&qb, g_q);
    cudaGetSymbolAddress(&kb, g_k);
    cudaGetSymbolAddress(&vb, g_v);
    cudaGetSymbolAddress(&ctxb, g_ctx);

    cvtx_kernel<<<2368, 256>>>(x, (__nv_bfloat16*)xb, M_ROWS * D_SZ / 4);
    cvt4w_kernel<<<dim3((D_SZ * D_SZ / 4) / 256, 4), 256>>>(
        Wq, Wk, Wv, Wo,
        (__nv_bfloat16*)wq, (__nv_bfloat16*)wk, (__nv_bfloat16*)wv, (__nv_bfloat16*)wo);

    cudaFuncSetAttribute(qkv_gemm_kernel, cudaFuncAttributeMaxDynamicSharedMemorySize, SMEM_GEMM);
    qkv_gemm_kernel<<<dim3(24, M_ROWS / BM), 256, SMEM_GEMM>>>(
        (const __nv_bfloat16*)xb,
        (const __nv_bfloat16*)wq, (const __nv_bfloat16*)wk, (const __nv_bfloat16*)wv,
        bq, bk, bv,
        (__nv_bfloat16*)qb, (__nv_bfloat16*)kb, (__nv_bfloat16*)vb);

    cudaFuncSetAttribute(attn_kernel, cudaFuncAttributeMaxDynamicSharedMemorySize, SMEM_ATTN);
    attn_kernel<<<dim3(SW_SZ / AQ, H_SZ, B_SZ * W_SZ), 128, SMEM_ATTN>>>(
        (const __nv_bfloat16*)qb, (const __nv_bfloat16*)kb, (const __nv_bfloat16*)vb,
        (__nv_bfloat16*)ctxb);

    cudaFuncSetAttribute(oproj_gemm_kernel, cudaFuncAttributeMaxDynamicSharedMemorySize, SMEM_GEMM);
    oproj_gemm_kernel<<<dim3(D_SZ / BN, M_ROWS / BM), 256, SMEM_GEMM>>>(
        (const __nv_bfloat16*)ctxb, (const __nv_bfloat16*)wo, bo, x, out);

    ln_kernel<<<M_ROWS, 256>>>(out, gamma, beta);
}